// round 2
// baseline (speedup 1.0000x reference)
#include <cuda_runtime.h>
#include <cuda_bf16.h>

// Problem constants
#define B_    8
#define C_IN  64
#define C_OUT 128
#define H_IN  256
#define W_IN  256
#define H_OUT 128
#define W_OUT 128
#define M_MAP 800000
#define V_SEG 200000
#define N_PTS 50000

#define CICHUNK 8      // input-channel chunk held in smem
#define WOT 32         // wo tile per block

// Scratch: conv output in NHWC-flat layout [B*H_OUT*W_OUT, C_OUT] (67 MB)
__device__ __align__(256) float g_y[(size_t)B_ * H_OUT * W_OUT * C_OUT];
// Transposed weights: [ci][k][co] (294 KB) for vectorized smem fills
__device__ __align__(256) float g_wT[C_IN * 9 * C_OUT];

// ---------------------------------------------------------------------------
// Kernel 0: transpose weights (C_OUT,C_IN,3,3) -> [ci][k][co]
// ---------------------------------------------------------------------------
__global__ void wt_transpose_kernel(const float* __restrict__ w) {
    int idx = blockIdx.x * blockDim.x + threadIdx.x;
    int total = C_IN * 9 * C_OUT;
    if (idx >= total) return;
    int co = idx % C_OUT;
    int k  = (idx / C_OUT) % 9;
    int ci = idx / (9 * C_OUT);
    g_wT[idx] = w[(co * C_IN + ci) * 9 + k];
}

// ---------------------------------------------------------------------------
// Kernel 1: 3x3 stride-2 pad-1 conv + bias + ReLU, NCHW in -> NHWC-flat out
// Block: 256 threads computes (1 b, 1 ho, 32 wo, 128 co).
// Thread t: co4 = (t&31)*4, wo_l = (t>>5)*4  -> 4 wo x 4 co accumulators.
// ---------------------------------------------------------------------------
__global__ __launch_bounds__(256) void conv_kernel(
    const float* __restrict__ x,
    const float* __restrict__ bias)
{
    __shared__ float x_s[CICHUNK][3][66];
    __shared__ float w_s[CICHUNK][9][C_OUT];

    const int wt = blockIdx.x;    // 0..3
    const int ho = blockIdx.y;    // 0..127
    const int b  = blockIdx.z;    // 0..7
    const int t  = threadIdx.x;
    const int co4  = (t & 31) * 4;
    const int wo_l = (t >> 5) * 4;
    const int wb = wt * WOT;

    float acc[4][4];
    #pragma unroll
    for (int i = 0; i < 4; i++)
        #pragma unroll
        for (int j = 0; j < 4; j++)
            acc[i][j] = 0.0f;

    for (int cc = 0; cc < C_IN; cc += CICHUNK) {
        // --- cooperative load of input tile: [CICHUNK][3 rows][65 cols + pad]
        for (int idx = t; idx < CICHUNK * 3 * 66; idx += 256) {
            int c  = idx % 66;
            int r  = (idx / 66) % 3;
            int ci = idx / (3 * 66);
            int ih = 2 * ho - 1 + r;
            int iw = 2 * wb - 1 + c;
            float v = 0.0f;
            if (c < 65 && ih >= 0 && ih < H_IN && iw >= 0 && iw < W_IN)
                v = x[(((size_t)(b * C_IN + cc + ci)) * H_IN + ih) * W_IN + iw];
            x_s[ci][r][c] = v;
        }
        // --- cooperative load of weight chunk (vectorized, contiguous in g_wT)
        {
            const float4* src = (const float4*)&g_wT[(size_t)cc * 9 * C_OUT];
            float4* dst = (float4*)&w_s[0][0][0];
            for (int idx = t; idx < CICHUNK * 9 * C_OUT / 4; idx += 256)
                dst[idx] = src[idx];
        }
        __syncthreads();

        #pragma unroll
        for (int ci = 0; ci < CICHUNK; ci++) {
            #pragma unroll
            for (int kh = 0; kh < 3; kh++) {
                float xr[9];
                #pragma unroll
                for (int q = 0; q < 9; q++)
                    xr[q] = x_s[ci][kh][2 * wo_l + q];
                #pragma unroll
                for (int kw = 0; kw < 3; kw++) {
                    float4 wv = *(const float4*)&w_s[ci][kh * 3 + kw][co4];
                    #pragma unroll
                    for (int i = 0; i < 4; i++) {
                        float xv = xr[kw + 2 * i];
                        acc[i][0] = fmaf(xv, wv.x, acc[i][0]);
                        acc[i][1] = fmaf(xv, wv.y, acc[i][1]);
                        acc[i][2] = fmaf(xv, wv.z, acc[i][2]);
                        acc[i][3] = fmaf(xv, wv.w, acc[i][3]);
                    }
                }
            }
        }
        __syncthreads();
    }

    // --- epilogue: bias + ReLU, store NHWC-flat (float4 per wo)
    float4 bv = *(const float4*)&bias[co4];
    #pragma unroll
    for (int i = 0; i < 4; i++) {
        int wo = wb + wo_l + i;
        float4 o;
        o.x = fmaxf(acc[i][0] + bv.x, 0.0f);
        o.y = fmaxf(acc[i][1] + bv.y, 0.0f);
        o.z = fmaxf(acc[i][2] + bv.z, 0.0f);
        o.w = fmaxf(acc[i][3] + bv.w, 0.0f);
        size_t pix = ((size_t)(b * H_OUT + ho)) * W_OUT + wo;
        *(float4*)&g_y[pix * C_OUT + co4] = o;
    }
}

// ---------------------------------------------------------------------------
// Kernel 2: fused gather + flattened double segment-max + additive fusion.
// One warp per 3D point. CSR-within-CSR => pixel range for point n is
// [a_ptr[v_ptr[n]], a_ptr[v_ptr[n+1]]). All values >= 0 (post-ReLU), so
// 0-initialized max == reference's isfinite->0 handling at both levels.
// Lane handles channels [lane*4, lane*4+4) as one float4.
// ---------------------------------------------------------------------------
__global__ __launch_bounds__(256) void pool_fuse_kernel(
    const float* __restrict__ x3d,
    const int*   __restrict__ fm_idx,
    const int*   __restrict__ a_ptr,
    const int*   __restrict__ v_ptr,
    float*       __restrict__ out)
{
    int warp = (blockIdx.x * blockDim.x + threadIdx.x) >> 5;
    int lane = threadIdx.x & 31;
    if (warp >= N_PTS) return;

    int v0 = v_ptr[warp];
    int v1 = v_ptr[warp + 1];
    int lo = a_ptr[v0];
    int hi = a_ptr[v1];

    float4 acc = make_float4(0.0f, 0.0f, 0.0f, 0.0f);
    int i = lo;
    // 4-wide unroll for MLP on the dependent idx->row loads
    for (; i + 4 <= hi; i += 4) {
        int r0 = fm_idx[i + 0];
        int r1 = fm_idx[i + 1];
        int r2 = fm_idx[i + 2];
        int r3 = fm_idx[i + 3];
        float4 y0 = *(const float4*)&g_y[(size_t)r0 * C_OUT + lane * 4];
        float4 y1 = *(const float4*)&g_y[(size_t)r1 * C_OUT + lane * 4];
        float4 y2 = *(const float4*)&g_y[(size_t)r2 * C_OUT + lane * 4];
        float4 y3 = *(const float4*)&g_y[(size_t)r3 * C_OUT + lane * 4];
        acc.x = fmaxf(fmaxf(fmaxf(acc.x, y0.x), fmaxf(y1.x, y2.x)), y3.x);
        acc.y = fmaxf(fmaxf(fmaxf(acc.y, y0.y), fmaxf(y1.y, y2.y)), y3.y);
        acc.z = fmaxf(fmaxf(fmaxf(acc.z, y0.z), fmaxf(y1.z, y2.z)), y3.z);
        acc.w = fmaxf(fmaxf(fmaxf(acc.w, y0.w), fmaxf(y1.w, y2.w)), y3.w);
    }
    for (; i < hi; i++) {
        int r = fm_idx[i];
        float4 yv = *(const float4*)&g_y[(size_t)r * C_OUT + lane * 4];
        acc.x = fmaxf(acc.x, yv.x);
        acc.y = fmaxf(acc.y, yv.y);
        acc.z = fmaxf(acc.z, yv.z);
        acc.w = fmaxf(acc.w, yv.w);
    }

    float4 xv = *(const float4*)&x3d[(size_t)warp * C_OUT + lane * 4];
    float4 o = make_float4(acc.x + xv.x, acc.y + xv.y, acc.z + xv.z, acc.w + xv.w);
    *(float4*)&out[(size_t)warp * C_OUT + lane * 4] = o;
}

// ---------------------------------------------------------------------------
// Launch
// Input order (metadata): x, w, b, x_3d, fm_idx, a_ptr, v_ptr
// ---------------------------------------------------------------------------
extern "C" void kernel_launch(void* const* d_in, const int* in_sizes, int n_in,
                              void* d_out, int out_size)
{
    const float* x      = (const float*)d_in[0];
    const float* w      = (const float*)d_in[1];
    const float* bias   = (const float*)d_in[2];
    const float* x3d    = (const float*)d_in[3];
    const int*   fm_idx = (const int*)d_in[4];
    const int*   a_ptr  = (const int*)d_in[5];
    const int*   v_ptr  = (const int*)d_in[6];
    float* out = (float*)d_out;

    // K0: weight transpose (73728 elems)
    wt_transpose_kernel<<<(C_IN * 9 * C_OUT + 255) / 256, 256>>>(w);

    // K1: conv + bias + relu -> g_y (NHWC-flat)
    dim3 cgrid(W_OUT / WOT, H_OUT, B_);
    conv_kernel<<<cgrid, 256>>>(x, bias);

    // K2: fused gather + double segment-max + add
    int nblocks = (N_PTS + 7) / 8;   // 8 warps per 256-thread block
    pool_fuse_kernel<<<nblocks, 256>>>(x3d, fm_idx, a_ptr, v_ptr, out);
}

// round 3
// speedup vs baseline: 1.0069x; 1.0069x over previous
#include <cuda_runtime.h>
#include <cuda_bf16.h>

// Problem constants
#define B_    8
#define C_IN  64
#define C_OUT 128
#define H_IN  256
#define W_IN  256
#define H_OUT 128
#define W_OUT 128
#define M_MAP 800000
#define V_SEG 200000
#define N_PTS 50000

#define CICHUNK 8      // input-channel chunk held in smem
#define WOT 32         // wo tile per block

// Scratch: conv output in NHWC-flat layout [B*H_OUT*W_OUT, C_OUT] (67 MB)
__device__ __align__(256) float g_y[(size_t)B_ * H_OUT * W_OUT * C_OUT];
// Transposed weights: [ci][k][co] (294 KB) for vectorized smem fills
__device__ __align__(256) float g_wT[C_IN * 9 * C_OUT];

// ---------------------------------------------------------------------------
// Kernel 0: transpose weights (C_OUT,C_IN,3,3) -> [ci][k][co]
// ---------------------------------------------------------------------------
__global__ void wt_transpose_kernel(const float* __restrict__ w) {
    int idx = blockIdx.x * blockDim.x + threadIdx.x;
    int total = C_IN * 9 * C_OUT;
    if (idx >= total) return;
    int co = idx % C_OUT;
    int k  = (idx / C_OUT) % 9;
    int ci = idx / (9 * C_OUT);
    g_wT[idx] = w[(co * C_IN + ci) * 9 + k];
}

// ---------------------------------------------------------------------------
// Kernel 1: 3x3 stride-2 pad-1 conv + bias + ReLU, NCHW in -> NHWC-flat out
// Block: 256 threads computes (1 b, 1 ho, 32 wo, 128 co).
// Thread t: co4 = (t&31)*4, wo_l = (t>>5)*4  -> 4 wo x 4 co accumulators.
// ---------------------------------------------------------------------------
__global__ __launch_bounds__(256) void conv_kernel(
    const float* __restrict__ x,
    const float* __restrict__ bias)
{
    __shared__ float x_s[CICHUNK][3][66];
    __shared__ float w_s[CICHUNK][9][C_OUT];

    const int wt = blockIdx.x;    // 0..3
    const int ho = blockIdx.y;    // 0..127
    const int b  = blockIdx.z;    // 0..7
    const int t  = threadIdx.x;
    const int co4  = (t & 31) * 4;
    const int wo_l = (t >> 5) * 4;
    const int wb = wt * WOT;

    float acc[4][4];
    #pragma unroll
    for (int i = 0; i < 4; i++)
        #pragma unroll
        for (int j = 0; j < 4; j++)
            acc[i][j] = 0.0f;

    for (int cc = 0; cc < C_IN; cc += CICHUNK) {
        // --- cooperative load of input tile: [CICHUNK][3 rows][65 cols + pad]
        for (int idx = t; idx < CICHUNK * 3 * 66; idx += 256) {
            int c  = idx % 66;
            int r  = (idx / 66) % 3;
            int ci = idx / (3 * 66);
            int ih = 2 * ho - 1 + r;
            int iw = 2 * wb - 1 + c;
            float v = 0.0f;
            if (c < 65 && ih >= 0 && ih < H_IN && iw >= 0 && iw < W_IN)
                v = x[(((size_t)(b * C_IN + cc + ci)) * H_IN + ih) * W_IN + iw];
            x_s[ci][r][c] = v;
        }
        // --- cooperative load of weight chunk (vectorized, contiguous in g_wT)
        {
            const float4* src = (const float4*)&g_wT[(size_t)cc * 9 * C_OUT];
            float4* dst = (float4*)&w_s[0][0][0];
            for (int idx = t; idx < CICHUNK * 9 * C_OUT / 4; idx += 256)
                dst[idx] = src[idx];
        }
        __syncthreads();

        #pragma unroll
        for (int ci = 0; ci < CICHUNK; ci++) {
            #pragma unroll
            for (int kh = 0; kh < 3; kh++) {
                float xr[9];
                #pragma unroll
                for (int q = 0; q < 9; q++)
                    xr[q] = x_s[ci][kh][2 * wo_l + q];
                #pragma unroll
                for (int kw = 0; kw < 3; kw++) {
                    float4 wv = *(const float4*)&w_s[ci][kh * 3 + kw][co4];
                    #pragma unroll
                    for (int i = 0; i < 4; i++) {
                        float xv = xr[kw + 2 * i];
                        acc[i][0] = fmaf(xv, wv.x, acc[i][0]);
                        acc[i][1] = fmaf(xv, wv.y, acc[i][1]);
                        acc[i][2] = fmaf(xv, wv.z, acc[i][2]);
                        acc[i][3] = fmaf(xv, wv.w, acc[i][3]);
                    }
                }
            }
        }
        __syncthreads();
    }

    // --- epilogue: bias + ReLU, store NHWC-flat (float4 per wo)
    float4 bv = *(const float4*)&bias[co4];
    #pragma unroll
    for (int i = 0; i < 4; i++) {
        int wo = wb + wo_l + i;
        float4 o;
        o.x = fmaxf(acc[i][0] + bv.x, 0.0f);
        o.y = fmaxf(acc[i][1] + bv.y, 0.0f);
        o.z = fmaxf(acc[i][2] + bv.z, 0.0f);
        o.w = fmaxf(acc[i][3] + bv.w, 0.0f);
        size_t pix = ((size_t)(b * H_OUT + ho)) * W_OUT + wo;
        *(float4*)&g_y[pix * C_OUT + co4] = o;
    }
}

// ---------------------------------------------------------------------------
// Kernel 2: fused gather + flattened double segment-max + additive fusion.
// One warp per 3D point. CSR-within-CSR => pixel range for point n is
// [a_ptr[v_ptr[n]], a_ptr[v_ptr[n+1]]). All values >= 0 (post-ReLU), so
// 0-initialized max == reference's isfinite->0 handling at both levels.
// Lane handles channels [lane*4, lane*4+4) as one float4.
// ---------------------------------------------------------------------------
__global__ __launch_bounds__(256) void pool_fuse_kernel(
    const float* __restrict__ x3d,
    const int*   __restrict__ fm_idx,
    const int*   __restrict__ a_ptr,
    const int*   __restrict__ v_ptr,
    float*       __restrict__ out)
{
    int warp = (blockIdx.x * blockDim.x + threadIdx.x) >> 5;
    int lane = threadIdx.x & 31;
    if (warp >= N_PTS) return;

    int v0 = v_ptr[warp];
    int v1 = v_ptr[warp + 1];
    int lo = a_ptr[v0];
    int hi = a_ptr[v1];

    float4 acc = make_float4(0.0f, 0.0f, 0.0f, 0.0f);
    int i = lo;
    // 4-wide unroll for MLP on the dependent idx->row loads
    for (; i + 4 <= hi; i += 4) {
        int r0 = fm_idx[i + 0];
        int r1 = fm_idx[i + 1];
        int r2 = fm_idx[i + 2];
        int r3 = fm_idx[i + 3];
        float4 y0 = *(const float4*)&g_y[(size_t)r0 * C_OUT + lane * 4];
        float4 y1 = *(const float4*)&g_y[(size_t)r1 * C_OUT + lane * 4];
        float4 y2 = *(const float4*)&g_y[(size_t)r2 * C_OUT + lane * 4];
        float4 y3 = *(const float4*)&g_y[(size_t)r3 * C_OUT + lane * 4];
        acc.x = fmaxf(fmaxf(fmaxf(acc.x, y0.x), fmaxf(y1.x, y2.x)), y3.x);
        acc.y = fmaxf(fmaxf(fmaxf(acc.y, y0.y), fmaxf(y1.y, y2.y)), y3.y);
        acc.z = fmaxf(fmaxf(fmaxf(acc.z, y0.z), fmaxf(y1.z, y2.z)), y3.z);
        acc.w = fmaxf(fmaxf(fmaxf(acc.w, y0.w), fmaxf(y1.w, y2.w)), y3.w);
    }
    for (; i < hi; i++) {
        int r = fm_idx[i];
        float4 yv = *(const float4*)&g_y[(size_t)r * C_OUT + lane * 4];
        acc.x = fmaxf(acc.x, yv.x);
        acc.y = fmaxf(acc.y, yv.y);
        acc.z = fmaxf(acc.z, yv.z);
        acc.w = fmaxf(acc.w, yv.w);
    }

    float4 xv = *(const float4*)&x3d[(size_t)warp * C_OUT + lane * 4];
    float4 o = make_float4(acc.x + xv.x, acc.y + xv.y, acc.z + xv.z, acc.w + xv.w);
    *(float4*)&out[(size_t)warp * C_OUT + lane * 4] = o;
}

// ---------------------------------------------------------------------------
// Launch
// Input order (metadata): x, w, b, x_3d, fm_idx, a_ptr, v_ptr
// ---------------------------------------------------------------------------
extern "C" void kernel_launch(void* const* d_in, const int* in_sizes, int n_in,
                              void* d_out, int out_size)
{
    const float* x      = (const float*)d_in[0];
    const float* w      = (const float*)d_in[1];
    const float* bias   = (const float*)d_in[2];
    const float* x3d    = (const float*)d_in[3];
    const int*   fm_idx = (const int*)d_in[4];
    const int*   a_ptr  = (const int*)d_in[5];
    const int*   v_ptr  = (const int*)d_in[6];
    float* out = (float*)d_out;

    // K0: weight transpose (73728 elems)
    wt_transpose_kernel<<<(C_IN * 9 * C_OUT + 255) / 256, 256>>>(w);

    // K1: conv + bias + relu -> g_y (NHWC-flat)
    dim3 cgrid(W_OUT / WOT, H_OUT, B_);
    conv_kernel<<<cgrid, 256>>>(x, bias);

    // K2: fused gather + double segment-max + add
    int nblocks = (N_PTS + 7) / 8;   // 8 warps per 256-thread block
    pool_fuse_kernel<<<nblocks, 256>>>(x3d, fm_idx, a_ptr, v_ptr, out);
}

// round 4
// speedup vs baseline: 1.1101x; 1.1025x over previous
#include <cuda_runtime.h>
#include <cuda_bf16.h>

// Problem constants
#define B_    8
#define C_IN  64
#define C_OUT 128
#define H_IN  256
#define W_IN  256
#define H_OUT 128
#define W_OUT 128
#define M_MAP 800000
#define V_SEG 200000
#define N_PTS 50000

#define CICHUNK 8      // input-channel chunk held in smem
#define WOB 64         // wo tile per block (8 warps x 8 wo each)
#define XCOLS 132      // 129 valid cols padded to 16B-multiple stride

// Scratch: conv output in NHWC-flat layout [B*H_OUT*W_OUT, C_OUT] (67 MB)
__device__ __align__(256) float g_y[(size_t)B_ * H_OUT * W_OUT * C_OUT];
// Transposed weights: [ci][k][co] (294 KB) for vectorized smem fills
__device__ __align__(256) float g_wT[C_IN * 9 * C_OUT];

// ---------------------------------------------------------------------------
// Packed fp32x2 helpers (Blackwell FFMA2 — only reachable via PTX)
// ---------------------------------------------------------------------------
__device__ __forceinline__ unsigned long long bcast2(float x) {
    unsigned long long r;
    asm("mov.b64 %0, {%1, %1};" : "=l"(r) : "f"(x));
    return r;
}
__device__ __forceinline__ void fma2(unsigned long long& d,
                                     unsigned long long a,
                                     unsigned long long b) {
    asm("fma.rn.f32x2 %0, %1, %2, %0;" : "+l"(d) : "l"(a), "l"(b));
}
__device__ __forceinline__ void unpack2(unsigned long long v, float& lo, float& hi) {
    asm("mov.b64 {%0, %1}, %2;" : "=f"(lo), "=f"(hi) : "l"(v));
}

// ---------------------------------------------------------------------------
// Kernel 0: transpose weights (C_OUT,C_IN,3,3) -> [ci][k][co]
// ---------------------------------------------------------------------------
__global__ void wt_transpose_kernel(const float* __restrict__ w) {
    int idx = blockIdx.x * blockDim.x + threadIdx.x;
    int total = C_IN * 9 * C_OUT;
    if (idx >= total) return;
    int co = idx % C_OUT;
    int k  = (idx / C_OUT) % 9;
    int ci = idx / (9 * C_OUT);
    g_wT[idx] = w[(co * C_IN + ci) * 9 + k];
}

// ---------------------------------------------------------------------------
// Kernel 1: 3x3 stride-2 pad-1 conv + bias + ReLU, NCHW in -> NHWC-flat out.
// Block: 256 threads computes (1 b, 1 ho, 64 wo, 128 co).
// Warp w handles wo [w*8, w*8+8); lane l handles co [l*4, l*4+4).
// Inner math uses packed fp32x2 FMA (FFMA2): accumulators are co-pairs.
// ---------------------------------------------------------------------------
__global__ __launch_bounds__(256) void conv_kernel(
    const float* __restrict__ x,
    const float* __restrict__ bias)
{
    extern __shared__ float smem_dyn[];
    float (*x_s)[3][XCOLS]  = (float (*)[3][XCOLS])smem_dyn;                       // [CICHUNK][3][132]
    float (*w_s)[9][C_OUT]  = (float (*)[9][C_OUT])(smem_dyn + CICHUNK * 3 * XCOLS); // [CICHUNK][9][128]

    const int ho = blockIdx.y;    // 0..127
    const int b  = blockIdx.z;    // 0..7
    const int t  = threadIdx.x;
    const int lane = t & 31;
    const int warp = t >> 5;
    const int co4  = lane * 4;
    const int wo_l = warp * 8;                 // 8 wo per warp-thread
    const int wb   = blockIdx.x * WOB;

    unsigned long long acc[8][2];
    const unsigned long long z2 = bcast2(0.0f);
    #pragma unroll
    for (int i = 0; i < 8; i++) { acc[i][0] = z2; acc[i][1] = z2; }

    for (int cc = 0; cc < C_IN; cc += CICHUNK) {
        // --- cooperative load of input tile: [CICHUNK][3 rows][129 cols]
        for (int idx = t; idx < CICHUNK * 3 * XCOLS; idx += 256) {
            int c  = idx % XCOLS;
            int r  = (idx / XCOLS) % 3;
            int ci = idx / (3 * XCOLS);
            int ih = 2 * ho - 1 + r;
            int iw = 2 * wb - 1 + c;
            float v = 0.0f;
            if (c < 129 && ih >= 0 && ih < H_IN && iw >= 0 && iw < W_IN)
                v = x[(((size_t)(b * C_IN + cc + ci)) * H_IN + ih) * W_IN + iw];
            x_s[ci][r][c] = v;
        }
        // --- cooperative load of weight chunk (vectorized, contiguous in g_wT)
        {
            const float4* src = (const float4*)&g_wT[(size_t)cc * 9 * C_OUT];
            float4* dst = (float4*)&w_s[0][0][0];
            for (int idx = t; idx < CICHUNK * 9 * C_OUT / 4; idx += 256)
                dst[idx] = src[idx];
        }
        __syncthreads();

        #pragma unroll
        for (int ci = 0; ci < CICHUNK; ci++) {
            #pragma unroll
            for (int kh = 0; kh < 3; kh++) {
                // x row slice for this warp: cols [2*wo_l, 2*wo_l+16]
                const float* xrow = &x_s[ci][kh][2 * wo_l];   // warp-uniform addr (broadcast LDS)
                float4 xa = *(const float4*)(xrow + 0);
                float4 xb = *(const float4*)(xrow + 4);
                float4 xc = *(const float4*)(xrow + 8);
                float4 xd = *(const float4*)(xrow + 12);
                float  xe = xrow[16];
                float xr[17] = {xa.x, xa.y, xa.z, xa.w,
                                xb.x, xb.y, xb.z, xb.w,
                                xc.x, xc.y, xc.z, xc.w,
                                xd.x, xd.y, xd.z, xd.w, xe};
                // weight co-pairs for the 3 kw taps (8B halves of the float4)
                ulonglong2 w0 = *(const ulonglong2*)&w_s[ci][kh * 3 + 0][co4];
                ulonglong2 w1 = *(const ulonglong2*)&w_s[ci][kh * 3 + 1][co4];
                ulonglong2 w2 = *(const ulonglong2*)&w_s[ci][kh * 3 + 2][co4];
                #pragma unroll
                for (int i = 0; i < 8; i++) {
                    unsigned long long p0 = bcast2(xr[2 * i + 0]);
                    unsigned long long p1 = bcast2(xr[2 * i + 1]);
                    unsigned long long p2 = bcast2(xr[2 * i + 2]);
                    fma2(acc[i][0], p0, w0.x); fma2(acc[i][1], p0, w0.y);
                    fma2(acc[i][0], p1, w1.x); fma2(acc[i][1], p1, w1.y);
                    fma2(acc[i][0], p2, w2.x); fma2(acc[i][1], p2, w2.y);
                }
            }
        }
        __syncthreads();
    }

    // --- epilogue: bias + ReLU, store NHWC-flat (float4 per wo)
    float4 bv = *(const float4*)&bias[co4];
    #pragma unroll
    for (int i = 0; i < 8; i++) {
        float a0, a1, a2, a3;
        unpack2(acc[i][0], a0, a1);
        unpack2(acc[i][1], a2, a3);
        float4 o;
        o.x = fmaxf(a0 + bv.x, 0.0f);
        o.y = fmaxf(a1 + bv.y, 0.0f);
        o.z = fmaxf(a2 + bv.z, 0.0f);
        o.w = fmaxf(a3 + bv.w, 0.0f);
        int wo = wb + wo_l + i;
        size_t pix = ((size_t)(b * H_OUT + ho)) * W_OUT + wo;
        *(float4*)&g_y[pix * C_OUT + co4] = o;
    }
}

// ---------------------------------------------------------------------------
// Kernel 2: fused gather + flattened double segment-max + additive fusion.
// One warp per 3D point. CSR-within-CSR => pixel range for point n is
// [a_ptr[v_ptr[n]], a_ptr[v_ptr[n+1]]). All values >= 0 (post-ReLU), so
// 0-initialized max == reference's isfinite->0 handling at both levels.
// Lane handles channels [lane*4, lane*4+4) as one float4.
// ---------------------------------------------------------------------------
__global__ __launch_bounds__(256) void pool_fuse_kernel(
    const float* __restrict__ x3d,
    const int*   __restrict__ fm_idx,
    const int*   __restrict__ a_ptr,
    const int*   __restrict__ v_ptr,
    float*       __restrict__ out)
{
    int warp = (blockIdx.x * blockDim.x + threadIdx.x) >> 5;
    int lane = threadIdx.x & 31;
    if (warp >= N_PTS) return;

    int v0 = v_ptr[warp];
    int v1 = v_ptr[warp + 1];
    int lo = a_ptr[v0];
    int hi = a_ptr[v1];

    float4 acc = make_float4(0.0f, 0.0f, 0.0f, 0.0f);
    int i = lo;
    // 4-wide unroll for MLP on the dependent idx->row loads
    for (; i + 4 <= hi; i += 4) {
        int r0 = fm_idx[i + 0];
        int r1 = fm_idx[i + 1];
        int r2 = fm_idx[i + 2];
        int r3 = fm_idx[i + 3];
        float4 y0 = *(const float4*)&g_y[(size_t)r0 * C_OUT + lane * 4];
        float4 y1 = *(const float4*)&g_y[(size_t)r1 * C_OUT + lane * 4];
        float4 y2 = *(const float4*)&g_y[(size_t)r2 * C_OUT + lane * 4];
        float4 y3 = *(const float4*)&g_y[(size_t)r3 * C_OUT + lane * 4];
        acc.x = fmaxf(fmaxf(fmaxf(acc.x, y0.x), fmaxf(y1.x, y2.x)), y3.x);
        acc.y = fmaxf(fmaxf(fmaxf(acc.y, y0.y), fmaxf(y1.y, y2.y)), y3.y);
        acc.z = fmaxf(fmaxf(fmaxf(acc.z, y0.z), fmaxf(y1.z, y2.z)), y3.z);
        acc.w = fmaxf(fmaxf(fmaxf(acc.w, y0.w), fmaxf(y1.w, y2.w)), y3.w);
    }
    for (; i < hi; i++) {
        int r = fm_idx[i];
        float4 yv = *(const float4*)&g_y[(size_t)r * C_OUT + lane * 4];
        acc.x = fmaxf(acc.x, yv.x);
        acc.y = fmaxf(acc.y, yv.y);
        acc.z = fmaxf(acc.z, yv.z);
        acc.w = fmaxf(acc.w, yv.w);
    }

    float4 xv = *(const float4*)&x3d[(size_t)warp * C_OUT + lane * 4];
    float4 o = make_float4(acc.x + xv.x, acc.y + xv.y, acc.z + xv.z, acc.w + xv.w);
    *(float4*)&out[(size_t)warp * C_OUT + lane * 4] = o;
}

// ---------------------------------------------------------------------------
// Launch
// Input order (metadata): x, w, b, x_3d, fm_idx, a_ptr, v_ptr
// ---------------------------------------------------------------------------
extern "C" void kernel_launch(void* const* d_in, const int* in_sizes, int n_in,
                              void* d_out, int out_size)
{
    const float* x      = (const float*)d_in[0];
    const float* w      = (const float*)d_in[1];
    const float* bias   = (const float*)d_in[2];
    const float* x3d    = (const float*)d_in[3];
    const int*   fm_idx = (const int*)d_in[4];
    const int*   a_ptr  = (const int*)d_in[5];
    const int*   v_ptr  = (const int*)d_in[6];
    float* out = (float*)d_out;

    // K0: weight transpose (73728 elems)
    wt_transpose_kernel<<<(C_IN * 9 * C_OUT + 255) / 256, 256>>>(w);

    // K1: conv + bias + relu -> g_y (NHWC-flat). 49.5 KB smem -> dynamic.
    const int smem_bytes = (CICHUNK * 3 * XCOLS + CICHUNK * 9 * C_OUT) * (int)sizeof(float);
    cudaFuncSetAttribute(conv_kernel, cudaFuncAttributeMaxDynamicSharedMemorySize, smem_bytes);
    dim3 cgrid(W_OUT / WOB, H_OUT, B_);
    conv_kernel<<<cgrid, 256, smem_bytes>>>(x, bias);

    // K2: fused gather + double segment-max + add
    int nblocks = (N_PTS + 7) / 8;   // 8 warps per 256-thread block
    pool_fuse_kernel<<<nblocks, 256>>>(x3d, fm_idx, a_ptr, v_ptr, out);
}